// round 11
// baseline (speedup 1.0000x reference)
#include <cuda_runtime.h>
#include <cstdint>

// MultiScaleDeformableAttention — GB300
// value:              (8, 22223, 8, 32)  float32
// sampling_locations: (8, 900, 8, 4, 4, 2) float32
// attention_weights:  (8, 900, 8, 4, 4) float32
// out:                (8, 900, 256) float32
//
// Diagnosis of the 39us plateau: Phase-B LDG.128s touched 4 cache lines per
// instruction -> within-LDG replays at 2.07 cyc/wavefront ~= 26us of L1tex
// service. This version makes every value load a single-line LDG.32
// (lane = channel, 32 lanes x 4B = one 128B row) at the 1.0 cyc/wf rate:
//   Phase A: lane s (s<16) computes the FULL descriptor set for
//            (lvl,pt) = (s>>2, s&3) -> 4 offsets + 4 folded weights; all 16
//            sets computed in parallel in ~35 warp-instructions. Stored to a
//            ~512B per-warp smem slab.
//   Phase B: for each of 16 sets: 2 broadcast LDS.128 (offsets, weights),
//            4 scalar LDG.32 + 4 FMA. Scalar accumulator per lane(=channel),
//            no shuffle reduction, coalesced 128B store.

#define BS  8
#define NQ  900
#define NH  8
#define DC  32
#define NL  4
#define NPT 4
#define NKEYS 22223
#define KSF 256               // floats per key = NH*DC
#define NTASK (BS * NQ * NH)  // 57600

__global__ __launch_bounds__(256) void msda_kernel(
    const float* __restrict__ value,
    const float* __restrict__ loc,
    const float* __restrict__ aw,
    float* __restrict__ out)
{
    __shared__ int4   s_off[8][17];   // [warp][set] 4 corner offsets (padded)
    __shared__ float4 s_wt [8][17];   // [warp][set] 4 folded weights (padded)

    const int gtid = blockIdx.x * blockDim.x + threadIdx.x;
    const int task = gtid >> 5;              // (b*NQ+q)*NH + h
    const int lane = gtid & 31;              // channel
    if (task >= NTASK) return;
    const int wslot = threadIdx.x >> 5;

    const int h = task & (NH - 1);
    const int b = (task >> 3) / NQ;

    // base pointer for (b, h, channel=lane); add key*KSF per tap
    const float* __restrict__ vptr =
        value + ((size_t)(b * NKEYS) * NH + h) * DC + lane;
    const float2* __restrict__ loc2 = (const float2*)loc;

    // ---------------- Phase A: one descriptor set per lane ----------------
    {
        const int s   = lane & 15;           // set id (lanes 16-31 duplicate)
        const int lvl = s >> 2;

        const int W     = (lvl == 0) ? 167 : (lvl == 1) ? 84 : (lvl == 2) ? 42 : 21;
        const int H     = (lvl == 0) ? 100 : (lvl == 1) ? 50 : (lvl == 2) ? 25 : 13;
        const int start = (lvl == 0) ? 0 : (lvl == 1) ? 16700 : (lvl == 2) ? 20900 : 21950;

        const int li = task * (NL * NPT) + s;
        const float2 l2 = __ldg(loc2 + li);
        const float  w  = __ldg(aw + li);

        const float x = l2.x * (float)W - 0.5f;
        const float y = l2.y * (float)H - 0.5f;
        const float xf = floorf(x);
        const float yf = floorf(y);
        const int x0 = (int)xf;
        const int y0 = (int)yf;
        const int x1 = x0 + 1;
        const int y1 = y0 + 1;

        float wx1 = x - xf;
        float wx0 = 1.0f - wx1;
        float wy1 = y - yf;
        float wy0 = 1.0f - wy1;

        // branch-free OOB: clamp index, zero the edge weight
        if (x0 < 0 || x0 > W - 1) wx0 = 0.0f;
        if (x1 < 0 || x1 > W - 1) wx1 = 0.0f;
        if (y0 < 0 || y0 > H - 1) wy0 = 0.0f;
        if (y1 < 0 || y1 > H - 1) wy1 = 0.0f;
        const int x0c = min(max(x0, 0), W - 1);
        const int x1c = min(max(x1, 0), W - 1);
        const int y0c = min(max(y0, 0), H - 1);
        const int y1c = min(max(y1, 0), H - 1);

        const int r0 = start + y0c * W;
        const int r1 = start + y1c * W;

        if (lane < 16) {
            s_off[wslot][s] = make_int4((r0 + x0c) * KSF, (r0 + x1c) * KSF,
                                        (r1 + x0c) * KSF, (r1 + x1c) * KSF);
            s_wt [wslot][s] = make_float4(w * wx0 * wy0, w * wx1 * wy0,
                                          w * wx0 * wy1, w * wx1 * wy1);
        }
    }
    __syncwarp();

    // ---------------- Phase B: 64 single-line LDG.32 + FMA ----------------
    float acc = 0.0f;

    #pragma unroll 4
    for (int t = 0; t < 16; ++t) {
        const int4   o  = s_off[wslot][t];   // broadcast LDS.128
        const float4 ww = s_wt [wslot][t];   // broadcast LDS.128
        const float a = __ldg(vptr + o.x);
        const float c = __ldg(vptr + o.y);
        const float d = __ldg(vptr + o.z);
        const float e = __ldg(vptr + o.w);
        acc = fmaf(a, ww.x, acc);
        acc = fmaf(c, ww.y, acc);
        acc = fmaf(d, ww.z, acc);
        acc = fmaf(e, ww.w, acc);
    }

    // out[task*32 + lane]: 32 lanes x 4B = one coalesced 128B store
    out[(size_t)task * DC + lane] = acc;
}

extern "C" void kernel_launch(void* const* d_in, const int* in_sizes, int n_in,
                              void* d_out, int out_size)
{
    const float* value = (const float*)d_in[0];
    const float* loc   = (const float*)d_in[1];
    const float* aw    = (const float*)d_in[2];
    float* out         = (float*)d_out;

    const int threads = 256;
    const int blocks  = (NTASK * 32 + threads - 1) / threads;  // 7200
    msda_kernel<<<blocks, threads>>>(value, loc, aw, out);
}

// round 12
// speedup vs baseline: 1.3904x; 1.3904x over previous
#include <cuda_runtime.h>
#include <cstdint>

// MultiScaleDeformableAttention — GB300
// value:              (8, 22223, 8, 32)  float32
// sampling_locations: (8, 900, 8, 4, 4, 2) float32
// attention_weights:  (8, 900, 8, 4, 4) float32
// out:                (8, 900, 256) float32
//
// R9 design (pinned (b,h) CTAs + __ldcs on streaming levels, __ldg on the
// L1-resident small levels) ran 39.2us on only 128/148 SMs. This version
// keeps the identical per-task body but distributes work over exactly 148
// CTAs (one per SM): CTAs 0..127 = (b,h,half) pinned, 396 of 450 queries;
// CTAs 128..147 sweep the 6912 leftover query-tasks (mixed bh; small-level
// taps hit L2 since the whole small-level set is ~11MB chip-wide).

#define BS  8
#define NQ  900
#define NH  8
#define DC  32
#define NL  4
#define NPT 4
#define NKEYS 22223
#define KS4 (NH * DC / 4)        // float4s per key = 64
#define QHALF (NQ / 2)           // 450
#define QMAIN 396                // queries handled by the pinned CTA
#define QREST (QHALF - QMAIN)    // 54 leftover per (bh,half)
#define NEXTRA 20                // helper CTAs
#define TOTREST (128 * QREST)    // 6912 leftover tasks

__device__ __forceinline__ void process_task(
    int task,
    const float4* __restrict__ v4,       // value base for (b,h) + cp
    const float2* __restrict__ loc2,
    const float*  __restrict__ aw,
    float* __restrict__ out,
    int g, int cp)
{
    const int Hs[NL]     = {100, 50, 25, 13};
    const int Ws[NL]     = {167, 84, 42, 21};
    const int starts[NL] = {0, 16700, 20900, 21950};

    // ---------------- Phase A: tap descriptors ----------------
    int   o00[NL], o10[NL], o01[NL], o11[NL];
    float w00[NL], w10[NL], w01[NL], w11[NL];

    #pragma unroll
    for (int lvl = 0; lvl < NL; ++lvl) {
        const int H = Hs[lvl];
        const int W = Ws[lvl];
        const int start = starts[lvl];

        const int li = (task * NL + lvl) * NPT + g;
        const float2 l2 = __ldcs(loc2 + li);   // streaming: evict-first
        const float w   = __ldcs(aw + li);

        const float x = l2.x * (float)W - 0.5f;
        const float y = l2.y * (float)H - 0.5f;
        const float xf = floorf(x);
        const float yf = floorf(y);
        const int x0 = (int)xf;
        const int y0 = (int)yf;
        const int x1 = x0 + 1;
        const int y1 = y0 + 1;

        float wx1 = x - xf;
        float wx0 = 1.0f - wx1;
        float wy1 = y - yf;
        float wy0 = 1.0f - wy1;

        // branch-free OOB: clamp index, zero the edge weight
        if (x0 < 0 || x0 > W - 1) wx0 = 0.0f;
        if (x1 < 0 || x1 > W - 1) wx1 = 0.0f;
        if (y0 < 0 || y0 > H - 1) wy0 = 0.0f;
        if (y1 < 0 || y1 > H - 1) wy1 = 0.0f;
        const int x0c = min(max(x0, 0), W - 1);
        const int x1c = min(max(x1, 0), W - 1);
        const int y0c = min(max(y0, 0), H - 1);
        const int y1c = min(max(y1, 0), H - 1);

        w00[lvl] = w * wx0 * wy0;
        w10[lvl] = w * wx1 * wy0;
        w01[lvl] = w * wx0 * wy1;
        w11[lvl] = w * wx1 * wy1;

        const int r0 = start + y0c * W;
        const int r1 = start + y1c * W;
        o00[lvl] = (r0 + x0c) * KS4;
        o10[lvl] = (r0 + x1c) * KS4;
        o01[lvl] = (r1 + x0c) * KS4;
        o11[lvl] = (r1 + x1c) * KS4;
    }

    // ---------------- Phase B: gather + accumulate ----------------
    float4 acc = make_float4(0.f, 0.f, 0.f, 0.f);

    #pragma unroll
    for (int lvl = 0; lvl < NL; ++lvl) {
        float4 a, c, d, e;
        if (lvl < 2) {
            // streaming levels: evict-first, don't thrash L1
            a = __ldcs(v4 + o00[lvl]);
            c = __ldcs(v4 + o10[lvl]);
            d = __ldcs(v4 + o01[lvl]);
            e = __ldcs(v4 + o11[lvl]);
        } else {
            // small levels: cache-all (L1-resident per pinned (b,h))
            a = __ldg(v4 + o00[lvl]);
            c = __ldg(v4 + o10[lvl]);
            d = __ldg(v4 + o01[lvl]);
            e = __ldg(v4 + o11[lvl]);
        }
        const float wa = w00[lvl], wc = w10[lvl], wd = w01[lvl], we = w11[lvl];

        acc.x += a.x * wa + c.x * wc + d.x * wd + e.x * we;
        acc.y += a.y * wa + c.y * wc + d.y * wd + e.y * we;
        acc.z += a.z * wa + c.z * wc + d.z * wd + e.z * we;
        acc.w += a.w * wa + c.w * wc + d.w * wd + e.w * we;
    }

    // reduce the 4 point-groups (lanes cp, cp+8, cp+16, cp+24)
    #pragma unroll
    for (int m = 8; m <= 16; m <<= 1) {
        acc.x += __shfl_xor_sync(0xffffffffu, acc.x, m);
        acc.y += __shfl_xor_sync(0xffffffffu, acc.y, m);
        acc.z += __shfl_xor_sync(0xffffffffu, acc.z, m);
        acc.w += __shfl_xor_sync(0xffffffffu, acc.w, m);
    }

    if (g == 0) {
        ((float4*)out)[(size_t)task * (DC / 4) + cp] = acc;
    }
}

__global__ __launch_bounds__(1024, 1) void msda_kernel(
    const float* __restrict__ value,
    const float* __restrict__ loc,
    const float* __restrict__ aw,
    float* __restrict__ out)
{
    const int cid  = blockIdx.x;
    const int tid  = threadIdx.x;
    const int wid  = tid >> 5;
    const int lane = tid & 31;
    const int g  = lane >> 3;            // point within level (0..3)
    const int cp = lane & 7;             // channel quad (0..7)

    const float4* __restrict__ val4 = (const float4*)value;
    const float2* __restrict__ loc2 = (const float2*)loc;

    if (cid < 128) {
        // pinned CTA: one (b,h,half), queries [0, QMAIN)
        const int bh   = cid >> 1;
        const int half = cid & 1;
        const int b    = bh >> 3;
        const int h    = bh & (NH - 1);

        const float4* __restrict__ v4 =
            val4 + ((size_t)(b * NKEYS) * NH + h) * (DC / 4) + cp;

        for (int ql = wid; ql < QMAIN; ql += 32) {
            const int q    = half * QHALF + ql;
            const int task = (b * NQ + q) * NH + h;
            process_task(task, v4, loc2, aw, out, g, cp);
        }
    } else {
        // helper CTA: strided sweep over the leftover tasks
        const int j = cid - 128;         // 0..19
        for (int idx = wid; ; idx += 32) {
            const int t = j + idx * NEXTRA;      // flat leftover index
            if (t >= TOTREST) break;

            const int bhh  = t / QREST;          // (bh,half) id 0..127
            const int rem  = t - bhh * QREST;    // 0..53
            const int bh   = bhh >> 1;
            const int half = bhh & 1;
            const int b    = bh >> 3;
            const int h    = bh & (NH - 1);

            const int q    = half * QHALF + QMAIN + rem;
            const int task = (b * NQ + q) * NH + h;

            const float4* __restrict__ v4 =
                val4 + ((size_t)(b * NKEYS) * NH + h) * (DC / 4) + cp;
            process_task(task, v4, loc2, aw, out, g, cp);
        }
    }
}

extern "C" void kernel_launch(void* const* d_in, const int* in_sizes, int n_in,
                              void* d_out, int out_size)
{
    const float* value = (const float*)d_in[0];
    const float* loc   = (const float*)d_in[1];
    const float* aw    = (const float*)d_in[2];
    float* out         = (float*)d_out;

    // 128 pinned CTAs + 20 helper CTAs = 148 = one per SM
    msda_kernel<<<148, 1024>>>(value, loc, aw, out);
}

// round 13
// speedup vs baseline: 1.5615x; 1.1231x over previous
#include <cuda_runtime.h>
#include <cstdint>

// MultiScaleDeformableAttention — GB300
// value:              (8, 22223, 8, 32)  float32
// sampling_locations: (8, 900, 8, 4, 4, 2) float32
// attention_weights:  (8, 900, 8, 4, 4) float32
// out:                (8, 900, 256) float32
//
// R12 winner (148 pinned+helper CTAs) with a three-tier cache policy:
//   lvl-0  : __ldcs  (137MB chip-wide > L2 -> pure stream, evict-first)
//   lvl-1  : __ldcg  (33.6MB chip-wide, ~3.5x reuse -> keep in L2, skip L1)
//   lvl-2/3: __ldg   (169KB per pinned (b,h) -> L1-resident)
// CTAs 0..127 = (b,h,half) pinned, queries [0,396); CTAs 128..147 sweep the
// 6912 leftover tasks strided across (b,h).

#define BS  8
#define NQ  900
#define NH  8
#define DC  32
#define NL  4
#define NPT 4
#define NKEYS 22223
#define KS4 (NH * DC / 4)        // float4s per key = 64
#define QHALF (NQ / 2)           // 450
#define QMAIN 396                // queries handled by the pinned CTA
#define QREST (QHALF - QMAIN)    // 54 leftover per (bh,half)
#define NEXTRA 20                // helper CTAs
#define TOTREST (128 * QREST)    // 6912 leftover tasks

__device__ __forceinline__ float4 ldcg4(const float4* p) {
    return __ldcg(p);
}

__device__ __forceinline__ void process_task(
    int task,
    const float4* __restrict__ v4,       // value base for (b,h) + cp
    const float2* __restrict__ loc2,
    const float*  __restrict__ aw,
    float* __restrict__ out,
    int g, int cp)
{
    const int Hs[NL]     = {100, 50, 25, 13};
    const int Ws[NL]     = {167, 84, 42, 21};
    const int starts[NL] = {0, 16700, 20900, 21950};

    // ---------------- Phase A: tap descriptors ----------------
    int   o00[NL], o10[NL], o01[NL], o11[NL];
    float w00[NL], w10[NL], w01[NL], w11[NL];

    #pragma unroll
    for (int lvl = 0; lvl < NL; ++lvl) {
        const int H = Hs[lvl];
        const int W = Ws[lvl];
        const int start = starts[lvl];

        const int li = (task * NL + lvl) * NPT + g;
        const float2 l2 = __ldcs(loc2 + li);   // streaming: evict-first
        const float w   = __ldcs(aw + li);

        const float x = l2.x * (float)W - 0.5f;
        const float y = l2.y * (float)H - 0.5f;
        const float xf = floorf(x);
        const float yf = floorf(y);
        const int x0 = (int)xf;
        const int y0 = (int)yf;
        const int x1 = x0 + 1;
        const int y1 = y0 + 1;

        float wx1 = x - xf;
        float wx0 = 1.0f - wx1;
        float wy1 = y - yf;
        float wy0 = 1.0f - wy1;

        // branch-free OOB: clamp index, zero the edge weight
        if (x0 < 0 || x0 > W - 1) wx0 = 0.0f;
        if (x1 < 0 || x1 > W - 1) wx1 = 0.0f;
        if (y0 < 0 || y0 > H - 1) wy0 = 0.0f;
        if (y1 < 0 || y1 > H - 1) wy1 = 0.0f;
        const int x0c = min(max(x0, 0), W - 1);
        const int x1c = min(max(x1, 0), W - 1);
        const int y0c = min(max(y0, 0), H - 1);
        const int y1c = min(max(y1, 0), H - 1);

        w00[lvl] = w * wx0 * wy0;
        w10[lvl] = w * wx1 * wy0;
        w01[lvl] = w * wx0 * wy1;
        w11[lvl] = w * wx1 * wy1;

        const int r0 = start + y0c * W;
        const int r1 = start + y1c * W;
        o00[lvl] = (r0 + x0c) * KS4;
        o10[lvl] = (r0 + x1c) * KS4;
        o01[lvl] = (r1 + x0c) * KS4;
        o11[lvl] = (r1 + x1c) * KS4;
    }

    // ---------------- Phase B: gather + accumulate ----------------
    float4 acc = make_float4(0.f, 0.f, 0.f, 0.f);

    #pragma unroll
    for (int lvl = 0; lvl < NL; ++lvl) {
        float4 a, c, d, e;
        if (lvl == 0) {
            // pure stream: evict-first everywhere
            a = __ldcs(v4 + o00[lvl]);
            c = __ldcs(v4 + o10[lvl]);
            d = __ldcs(v4 + o01[lvl]);
            e = __ldcs(v4 + o11[lvl]);
        } else if (lvl == 1) {
            // L2-resident tier: cache in L2, bypass L1
            a = ldcg4(v4 + o00[lvl]);
            c = ldcg4(v4 + o10[lvl]);
            d = ldcg4(v4 + o01[lvl]);
            e = ldcg4(v4 + o11[lvl]);
        } else {
            // small levels: cache-all (L1-resident per pinned (b,h))
            a = __ldg(v4 + o00[lvl]);
            c = __ldg(v4 + o10[lvl]);
            d = __ldg(v4 + o01[lvl]);
            e = __ldg(v4 + o11[lvl]);
        }
        const float wa = w00[lvl], wc = w10[lvl], wd = w01[lvl], we = w11[lvl];

        acc.x += a.x * wa + c.x * wc + d.x * wd + e.x * we;
        acc.y += a.y * wa + c.y * wc + d.y * wd + e.y * we;
        acc.z += a.z * wa + c.z * wc + d.z * wd + e.z * we;
        acc.w += a.w * wa + c.w * wc + d.w * wd + e.w * we;
    }

    // reduce the 4 point-groups (lanes cp, cp+8, cp+16, cp+24)
    #pragma unroll
    for (int m = 8; m <= 16; m <<= 1) {
        acc.x += __shfl_xor_sync(0xffffffffu, acc.x, m);
        acc.y += __shfl_xor_sync(0xffffffffu, acc.y, m);
        acc.z += __shfl_xor_sync(0xffffffffu, acc.z, m);
        acc.w += __shfl_xor_sync(0xffffffffu, acc.w, m);
    }

    if (g == 0) {
        ((float4*)out)[(size_t)task * (DC / 4) + cp] = acc;
    }
}

__global__ __launch_bounds__(1024, 1) void msda_kernel(
    const float* __restrict__ value,
    const float* __restrict__ loc,
    const float* __restrict__ aw,
    float* __restrict__ out)
{
    const int cid  = blockIdx.x;
    const int tid  = threadIdx.x;
    const int wid  = tid >> 5;
    const int lane = tid & 31;
    const int g  = lane >> 3;            // point within level (0..3)
    const int cp = lane & 7;             // channel quad (0..7)

    const float4* __restrict__ val4 = (const float4*)value;
    const float2* __restrict__ loc2 = (const float2*)loc;

    if (cid < 128) {
        // pinned CTA: one (b,h,half), queries [0, QMAIN)
        const int bh   = cid >> 1;
        const int half = cid & 1;
        const int b    = bh >> 3;
        const int h    = bh & (NH - 1);

        const float4* __restrict__ v4 =
            val4 + ((size_t)(b * NKEYS) * NH + h) * (DC / 4) + cp;

        for (int ql = wid; ql < QMAIN; ql += 32) {
            const int q    = half * QHALF + ql;
            const int task = (b * NQ + q) * NH + h;
            process_task(task, v4, loc2, aw, out, g, cp);
        }
    } else {
        // helper CTA: strided sweep over the leftover tasks
        const int j = cid - 128;         // 0..19
        for (int idx = wid; ; idx += 32) {
            const int t = j + idx * NEXTRA;      // flat leftover index
            if (t >= TOTREST) break;

            const int bhh  = t / QREST;          // (bh,half) id 0..127
            const int rem  = t - bhh * QREST;    // 0..53
            const int bh   = bhh >> 1;
            const int half = bhh & 1;
            const int b    = bh >> 3;
            const int h    = bh & (NH - 1);

            const int q    = half * QHALF + QMAIN + rem;
            const int task = (b * NQ + q) * NH + h;

            const float4* __restrict__ v4 =
                val4 + ((size_t)(b * NKEYS) * NH + h) * (DC / 4) + cp;
            process_task(task, v4, loc2, aw, out, g, cp);
        }
    }
}

extern "C" void kernel_launch(void* const* d_in, const int* in_sizes, int n_in,
                              void* d_out, int out_size)
{
    const float* value = (const float*)d_in[0];
    const float* loc   = (const float*)d_in[1];
    const float* aw    = (const float*)d_in[2];
    float* out         = (float*)d_out;

    // 128 pinned CTAs + 20 helper CTAs = 148 = one per SM
    msda_kernel<<<148, 1024>>>(value, loc, aw, out);
}